// round 16
// baseline (speedup 1.0000x reference)
#include <cuda_runtime.h>
#include <cuda_bf16.h>
#include <math.h>
#include <stdint.h>

#define D_IN 5
#define H0 128
#define H1 64

// scratch: 4 arrays of [1024][128] fp32 (hl_chg, hr_chg, hl_dg, hr_dg)
__device__ float g_hbuf[4 * 1024 * 128];
// W1 hi/lo bf16, n-major padded: [branch][hi/lo][64 rows][136 cols]
__device__ __align__(16) __nv_bfloat16 g_w1[2][2][64 * 136];
// pre-split gemm operands: [op A/B][hi/lo][1024*1024] bf16
__device__ __align__(16) __nv_bfloat16 g_ops[2][2][1024 * 1024];

// ---------------------------------------------------------------------------
// PTX helpers (architecture-portable, sm_80-level)
// ---------------------------------------------------------------------------
__device__ __forceinline__ void mma_bf16(
    float& d0, float& d1, float& d2, float& d3,
    uint32_t a0, uint32_t a1, uint32_t a2, uint32_t a3,
    uint32_t b0, uint32_t b1)
{
    asm volatile(
        "mma.sync.aligned.m16n8k16.row.col.f32.bf16.bf16.f32 "
        "{%0,%1,%2,%3}, {%4,%5,%6,%7}, {%8,%9}, {%0,%1,%2,%3};"
        : "+f"(d0), "+f"(d1), "+f"(d2), "+f"(d3)
        : "r"(a0), "r"(a1), "r"(a2), "r"(a3), "r"(b0), "r"(b1));
}

// round-nearest split (W1 / gemm operands)
__device__ __forceinline__ void split2(float a, float b, uint32_t& hi, uint32_t& lo) {
    __nv_bfloat162 h = __float22bfloat162_rn(make_float2(a, b));
    float ra = a - __bfloat162float(h.x);
    float rb = b - __bfloat162float(h.y);
    __nv_bfloat162 l = __float22bfloat162_rn(make_float2(ra, rb));
    hi = *reinterpret_cast<uint32_t*>(&h);
    lo = *reinterpret_cast<uint32_t*>(&l);
}

// truncation split (pair act-gen hot path)
__device__ __forceinline__ void split2t(float a, float b, uint32_t& hi, uint32_t& lo) {
    uint32_t ia = __float_as_uint(a), ib = __float_as_uint(b);
    uint32_t h;
    asm("prmt.b32 %0, %1, %2, 0x7632;" : "=r"(h) : "r"(ia), "r"(ib));
    float ha = __uint_as_float(ia & 0xFFFF0000u);
    float hb = __uint_as_float(ib & 0xFFFF0000u);
    __nv_bfloat162 l = __float22bfloat162_rn(make_float2(a - ha, b - hb));
    hi = h;
    lo = *reinterpret_cast<uint32_t*>(&l);
}

__device__ __forceinline__ uint32_t smem_u32(const void* p) {
    uint32_t a;
    asm("{ .reg .u64 t; cvta.to.shared.u64 t, %1; cvt.u32.u64 %0, t; }"
        : "=r"(a) : "l"(p));
    return a;
}
__device__ __forceinline__ void cp_async16(uint32_t dst, const void* src) {
    asm volatile("cp.async.cg.shared.global [%0], [%1], 16;"
                 :: "r"(dst), "l"(src));
}
#define CP_COMMIT() asm volatile("cp.async.commit_group;" ::: "memory")
#define CP_WAIT(n)  asm volatile("cp.async.wait_group %0;" :: "n"(n) : "memory")

__device__ __forceinline__ void ldsm_x4(uint32_t& r0, uint32_t& r1,
                                        uint32_t& r2, uint32_t& r3, uint32_t a) {
    asm volatile("ldmatrix.sync.aligned.m8n8.x4.shared.b16 {%0,%1,%2,%3}, [%4];"
                 : "=r"(r0), "=r"(r1), "=r"(r2), "=r"(r3) : "r"(a));
}
__device__ __forceinline__ void ldsm_x4t(uint32_t& r0, uint32_t& r1,
                                         uint32_t& r2, uint32_t& r3, uint32_t a) {
    asm volatile("ldmatrix.sync.aligned.m8n8.x4.trans.shared.b16 {%0,%1,%2,%3}, [%4];"
                 : "=r"(r0), "=r"(r1), "=r"(r2), "=r"(r3) : "r"(a));
}
__device__ __forceinline__ uint32_t sw128(uint32_t bo) {
    return bo ^ ((bo >> 3) & 0x70);
}

// ---------------------------------------------------------------------------
// Kernel 1: flat element-parallel precompute (hbuf + W1 split)
// ---------------------------------------------------------------------------
#define HB_BLOCKS 2048
#define W1_ELEMS  (64 * 136)
#define W1_BLOCKS ((2 * W1_ELEMS + 255) / 256)

__global__ __launch_bounds__(256) void precompute_kernel(
    const float* __restrict__ X_ch, const float* __restrict__ X_g,
    const float* __restrict__ X_d,
    const float* __restrict__ W_chg0, const float* __restrict__ b_chg0,
    const float* __restrict__ W_dg0,  const float* __restrict__ b_dg0,
    const float* __restrict__ W_chg1, const float* __restrict__ W_dg1)
{
    int bid = blockIdx.x;
    if (bid < HB_BLOCKS) {
        int idx = bid * 256 + threadIdx.x;
        int a   = idx >> 17;
        int rem = idx & 131071;
        int row = rem >> 7;
        int k   = rem & 127;

        const float* X; const float* W; const float* b = nullptr;
        int woff;
        if (a == 0)      { X = X_ch; W = W_chg0; b = b_chg0; woff = 0; }
        else if (a == 1) { X = X_g;  W = W_chg0;             woff = D_IN; }
        else if (a == 2) { X = X_g;  W = W_dg0;  b = b_dg0;  woff = 0; }
        else             { X = X_d;  W = W_dg0;              woff = D_IN; }

        float v = b ? b[k] : 0.0f;
#pragma unroll
        for (int d = 0; d < D_IN; d++)
            v = fmaf(__ldg(&X[row * D_IN + d]), W[(woff + d) * H0 + k], v);
        g_hbuf[idx] = v;
    } else {
        int i = (bid - HB_BLOCKS) * 256 + threadIdx.x;
        if (i >= 2 * W1_ELEMS) return;
        int br = i / W1_ELEMS;
        int j  = i - br * W1_ELEMS;
        const float* W = br ? W_dg1 : W_chg1;
        int n = j / 136, kk = j % 136;
        float v = (kk < H0) ? W[kk * H1 + n] : 0.0f;
        __nv_bfloat16 h = __float2bfloat16(v);
        __nv_bfloat16 l = __float2bfloat16(v - __bfloat162float(h));
        g_w1[br][0][j] = h;
        g_w1[br][1][j] = l;
    }
}

// ---------------------------------------------------------------------------
// Kernel 2: pair MLP: bf16 3-product MMA (trunc split for A),
// 256 threads (8 warps) = 4 l x 2 r-halves, 16 pairs x 64 n per warp.
// r-tile per CTA = 256 (8 riter iterations) -> halved CTA count, halved
// redundant W1 staging. B via ldmatrix, shr cp.async double-buffered.
// ---------------------------------------------------------------------------
#define PAIR_SHR0  34816
#define PAIR_SHRSZ 17408
#define SMEM_PAIR  74240
#define PAIR_RITERS 8

__global__ __launch_bounds__(256, 3) void pair_mlp_mma(
    const float* __restrict__ b1a, const float* __restrict__ Wra,
    const float* __restrict__ bra, float* __restrict__ Aa,
    const float* __restrict__ b1b, const float* __restrict__ Wrb,
    const float* __restrict__ brb, float* __restrict__ Ab,
    int R)
{
    extern __shared__ char smem[];
    __nv_bfloat16* sw1hi = (__nv_bfloat16*)smem;
    float* shl = (float*)(smem + 69632);
    float* sb1 = (float*)(smem + 73728);
    float* swr = (float*)(smem + 73984);
    const uint32_t sbase = smem_u32(smem);

    const int branch = blockIdx.z;
    const float* g_hl = g_hbuf + (branch ? 2 : 0) * 1024 * H0;
    const float* g_hr = g_hbuf + (branch ? 3 : 1) * 1024 * H0;
    const float* b1 = branch ? b1b : b1a;
    const float* Wr = branch ? Wrb : Wra;
    const float* br = branch ? brb : bra;
    float* A = branch ? Ab : Aa;
    __nv_bfloat16* opHi = g_ops[branch][0];
    __nv_bfloat16* opLo = g_ops[branch][1];

    const int t    = threadIdx.x;
    const int wid  = t >> 5;
    const int lane = t & 31;
    const int lw   = wid >> 1;
    const int rh   = wid & 1;
    const int l0   = blockIdx.y * 4;
    const int rblk = blockIdx.x * 256;

    {
        const uint4* gw = (const uint4*)g_w1[branch][0];
        uint4* sw = (uint4*)sw1hi;
        for (int i = t; i < 2176; i += 256) sw[i] = gw[i];
    }
    if (t < 128) ((float4*)shl)[t] = ((const float4*)(g_hl + (size_t)l0 * H0))[t];
    if (t >= 128 && t < 128 + H1) { sb1[t - 128] = b1[t - 128]; swr[t - 128] = Wr[t - 128]; }

    const float* shl_l = shl + lw * H0;
    const float brv = br[0];

    const int kq = (lane & 3) * 2;
    const int rq = lane >> 2;

    const int btile = lane >> 3;
    const int bnoff = (btile >> 1) * 8 + (lane & 7);
    const int bkoff = (btile & 1) * 8;

    auto stage = [&](int riter, int buf) {
        const int rb = rblk + riter * 32;
        uint32_t dst0 = sbase + PAIR_SHR0 + buf * PAIR_SHRSZ;
#pragma unroll
        for (int i = t; i < 1024; i += 256) {
            int row = i >> 5, c4 = i & 31;
            cp_async16(dst0 + (uint32_t)(row * 136 + c4 * 4) * 4u,
                       g_hr + (size_t)(rb + row) * H0 + c4 * 4);
        }
    };

    stage(0, 0);
    CP_COMMIT();

    for (int riter = 0; riter < PAIR_RITERS; riter++) {
        __syncthreads();
        if (riter + 1 < PAIR_RITERS) {
            stage(riter + 1, (riter + 1) & 1);
            CP_COMMIT();
            CP_WAIT(1);
        } else {
            CP_WAIT(0);
        }
        __syncthreads();

        const float* shr = (const float*)(smem + PAIR_SHR0 + (riter & 1) * PAIR_SHRSZ);
        const int rbase = rblk + riter * 32;

        float acc[8][4];
#pragma unroll
        for (int nt = 0; nt < 8; nt++)
#pragma unroll
            for (int c = 0; c < 4; c++) acc[nt][c] = 0.0f;

#pragma unroll
        for (int kt = 0; kt < 8; kt++) {
            const int kk = kt * 16 + kq;

            uint32_t ahi[4], alo[4];
            {
                float2 y0 = *(const float2*)(shl_l + kk);
                float2 y1 = *(const float2*)(shl_l + kk + 8);
                int r_lo = rh * 16 + rq;
                const float* p0 = shr + r_lo * 136 + kk;
                const float* p1 = shr + (r_lo + 8) * 136 + kk;
                float2 x00 = *(const float2*)p0;
                float2 x01 = *(const float2*)(p0 + 8);
                float2 x10 = *(const float2*)p1;
                float2 x11 = *(const float2*)(p1 + 8);
                split2t(fmaxf(x00.x + y0.x, 0.f), fmaxf(x00.y + y0.y, 0.f),
                        ahi[0], alo[0]);
                split2t(fmaxf(x10.x + y0.x, 0.f), fmaxf(x10.y + y0.y, 0.f),
                        ahi[1], alo[1]);
                split2t(fmaxf(x01.x + y1.x, 0.f), fmaxf(x01.y + y1.y, 0.f),
                        ahi[2], alo[2]);
                split2t(fmaxf(x11.x + y1.x, 0.f), fmaxf(x11.y + y1.y, 0.f),
                        ahi[3], alo[3]);
            }

#pragma unroll
            for (int g = 0; g < 4; g++) {
                uint32_t boff = (uint32_t)((g * 16 + bnoff) * 136
                                           + kt * 16 + bkoff) * 2u;
                uint32_t bh0, bh1, bh2, bh3, bl0, bl1, bl2, bl3;
                ldsm_x4(bh0, bh1, bh2, bh3, sbase + boff);
                ldsm_x4(bl0, bl1, bl2, bl3, sbase + 17408u + boff);

                int nt0 = 2 * g, nt1 = 2 * g + 1;
                mma_bf16(acc[nt0][0], acc[nt0][1], acc[nt0][2], acc[nt0][3],
                         ahi[0], ahi[1], ahi[2], ahi[3], bh0, bh1);
                mma_bf16(acc[nt0][0], acc[nt0][1], acc[nt0][2], acc[nt0][3],
                         ahi[0], ahi[1], ahi[2], ahi[3], bl0, bl1);
                mma_bf16(acc[nt0][0], acc[nt0][1], acc[nt0][2], acc[nt0][3],
                         alo[0], alo[1], alo[2], alo[3], bh0, bh1);
                mma_bf16(acc[nt1][0], acc[nt1][1], acc[nt1][2], acc[nt1][3],
                         ahi[0], ahi[1], ahi[2], ahi[3], bh2, bh3);
                mma_bf16(acc[nt1][0], acc[nt1][1], acc[nt1][2], acc[nt1][3],
                         ahi[0], ahi[1], ahi[2], ahi[3], bl2, bl3);
                mma_bf16(acc[nt1][0], acc[nt1][1], acc[nt1][2], acc[nt1][3],
                         alo[0], alo[1], alo[2], alo[3], bh2, bh3);
            }
        }

        // epilogue
        {
            float s0 = 0.0f, s1 = 0.0f;
#pragma unroll
            for (int nt = 0; nt < 8; nt++) {
                int j0 = nt * 8 + kq;
                float bb0 = sb1[j0], bb1 = sb1[j0 + 1];
                float ww0 = swr[j0], ww1 = swr[j0 + 1];
                s0 = fmaf(fmaxf(acc[nt][0] + bb0, 0.f), ww0, s0);
                s0 = fmaf(fmaxf(acc[nt][1] + bb1, 0.f), ww1, s0);
                s1 = fmaf(fmaxf(acc[nt][2] + bb0, 0.f), ww0, s1);
                s1 = fmaf(fmaxf(acc[nt][3] + bb1, 0.f), ww1, s1);
            }
            s0 += __shfl_xor_sync(0xffffffffu, s0, 1);
            s0 += __shfl_xor_sync(0xffffffffu, s0, 2);
            s1 += __shfl_xor_sync(0xffffffffu, s1, 1);
            s1 += __shfl_xor_sync(0xffffffffu, s1, 2);
            if ((lane & 3) == 0) {
                int r_lo = rbase + rh * 16 + rq;
                float x0 = s0 + brv;
                float x1 = s1 + brv;
                float e0 = (x0 > 0.0f) ? x0 : expm1f(x0);
                float e1 = (x1 > 0.0f) ? x1 : expm1f(x1);
                size_t rowoff = (size_t)(l0 + lw) * R;
                float* arow = A + rowoff;
                arow[r_lo]     = e0;
                arow[r_lo + 8] = e1;
                __nv_bfloat16 h0 = __float2bfloat16(e0);
                __nv_bfloat16 h1 = __float2bfloat16(e1);
                opHi[rowoff + r_lo]     = h0;
                opHi[rowoff + r_lo + 8] = h1;
                opLo[rowoff + r_lo]     = __float2bfloat16(e0 - __bfloat162float(h0));
                opLo[rowoff + r_lo + 8] = __float2bfloat16(e1 - __bfloat162float(h1));
            }
        }
    }
}

// ---------------------------------------------------------------------------
// Kernel 3: C = sigmoid(A @ B), bf16 3-product MMA, operands pre-split.
// 64m x 64n CTA tiles (256 CTAs), 32KB/stage double-buffered.
// ---------------------------------------------------------------------------
#define GS_STAGE 32768
#define GS_ALO   8192
#define GS_BHI   16384
#define GS_BLO   24576
#define SMEM_GEMM (2 * GS_STAGE)

__global__ __launch_bounds__(256, 2) void gemm_sigmoid_tc(
    float* __restrict__ C, int M, int N, int K)
{
    extern __shared__ char smem[];
    const uint32_t sb = smem_u32(smem);

    const __nv_bfloat16* gAhi = g_ops[0][0];
    const __nv_bfloat16* gAlo = g_ops[0][1];
    const __nv_bfloat16* gBhi = g_ops[1][0];
    const __nv_bfloat16* gBlo = g_ops[1][1];

    const int t    = threadIdx.x;
    const int wid  = t >> 5;
    const int lane = t & 31;
    const int m0 = blockIdx.y * 64, n0 = blockIdx.x * 64;
    const int wm = (wid >> 2) * 32;
    const int wn = (wid & 3) * 16;
    const int kq = (lane & 3) * 2;
    const int rq = lane >> 2;

    float acc[2][2][4];
#pragma unroll
    for (int mh = 0; mh < 2; mh++)
#pragma unroll
        for (int nt = 0; nt < 2; nt++)
#pragma unroll
            for (int c = 0; c < 4; c++) acc[mh][nt][c] = 0.0f;

    const int K64 = K >> 6;

    auto stage = [&](int kb, int buf) {
        uint32_t base = sb + buf * GS_STAGE;
#pragma unroll
        for (int i = t; i < 512; i += 256) {
            int m = i >> 3, c = i & 7;
            uint32_t sw = sw128((uint32_t)(m * 128 + c * 16));
            size_t off = (size_t)(m0 + m) * K + kb * 64 + c * 8;
            cp_async16(base + sw, gAhi + off);
            cp_async16(base + GS_ALO + sw, gAlo + off);
        }
#pragma unroll
        for (int i = t; i < 512; i += 256) {
            int k = i >> 3, c = i & 7;
            uint32_t sw = sw128((uint32_t)(k * 128 + c * 16));
            size_t off = (size_t)(kb * 64 + k) * N + n0 + c * 8;
            cp_async16(base + GS_BHI + sw, gBhi + off);
            cp_async16(base + GS_BLO + sw, gBlo + off);
        }
    };

    stage(0, 0);
    CP_COMMIT();

    for (int kb = 0; kb < K64; kb++) {
        if (kb + 1 < K64) {
            stage(kb + 1, (kb + 1) & 1);
            CP_COMMIT();
            CP_WAIT(1);
        } else {
            CP_WAIT(0);
        }
        __syncthreads();

        uint32_t base = sb + (kb & 1) * GS_STAGE;
#pragma unroll
        for (int kt = 0; kt < 4; kt++) {
            uint32_t ahi[2][4], alo[2][4];
#pragma unroll
            for (int mh = 0; mh < 2; mh++) {
                int row = wm + mh * 16 + (lane & 15);
                uint32_t sw = sw128((uint32_t)(row * 128 + kt * 32 + (lane >> 4) * 16));
                ldsm_x4(ahi[mh][0], ahi[mh][1], ahi[mh][2], ahi[mh][3], base + sw);
                ldsm_x4(alo[mh][0], alo[mh][1], alo[mh][2], alo[mh][3],
                        base + GS_ALO + sw);
            }
            uint32_t bh[2][2], bl[2][2];
            {
                int krow = kt * 16 + (lane & 15);
                uint32_t sw = sw128((uint32_t)(krow * 128 + wn * 2
                                               + (lane >> 4) * 16));
                uint32_t r0, r1, r2, r3;
                ldsm_x4t(r0, r1, r2, r3, base + GS_BHI + sw);
                bh[0][0] = r0; bh[0][1] = r1; bh[1][0] = r2; bh[1][1] = r3;
                ldsm_x4t(r0, r1, r2, r3, base + GS_BLO + sw);
                bl[0][0] = r0; bl[0][1] = r1; bl[1][0] = r2; bl[1][1] = r3;
            }
#pragma unroll
            for (int nt = 0; nt < 2; nt++)
#pragma unroll
                for (int mh = 0; mh < 2; mh++) {
                    mma_bf16(acc[mh][nt][0], acc[mh][nt][1],
                             acc[mh][nt][2], acc[mh][nt][3],
                             ahi[mh][0], ahi[mh][1], ahi[mh][2], ahi[mh][3],
                             bh[nt][0], bh[nt][1]);
                    mma_bf16(acc[mh][nt][0], acc[mh][nt][1],
                             acc[mh][nt][2], acc[mh][nt][3],
                             ahi[mh][0], ahi[mh][1], ahi[mh][2], ahi[mh][3],
                             bl[nt][0], bl[nt][1]);
                    mma_bf16(acc[mh][nt][0], acc[mh][nt][1],
                             acc[mh][nt][2], acc[mh][nt][3],
                             alo[mh][0], alo[mh][1], alo[mh][2], alo[mh][3],
                             bh[nt][0], bh[nt][1]);
                }
        }
        __syncthreads();
    }

#pragma unroll
    for (int mh = 0; mh < 2; mh++)
#pragma unroll
        for (int nt = 0; nt < 2; nt++) {
            int row = m0 + wm + mh * 16 + rq;
            int col = n0 + wn + nt * 8 + kq;
            float* r0p = &C[(size_t)row * N + col];
            float* r1p = &C[(size_t)(row + 8) * N + col];
            r0p[0] = 1.0f / (1.0f + __expf(-acc[mh][nt][0]));
            r0p[1] = 1.0f / (1.0f + __expf(-acc[mh][nt][1]));
            r1p[0] = 1.0f / (1.0f + __expf(-acc[mh][nt][2]));
            r1p[1] = 1.0f / (1.0f + __expf(-acc[mh][nt][3]));
        }
}

// ---------------------------------------------------------------------------
// Launch
// ---------------------------------------------------------------------------
extern "C" void kernel_launch(void* const* d_in, const int* in_sizes, int n_in,
                              void* d_out, int out_size)
{
    const float* X_ch   = (const float*)d_in[0];
    const float* X_g    = (const float*)d_in[1];
    const float* X_d    = (const float*)d_in[2];
    const float* W_chg0 = (const float*)d_in[3];
    const float* b_chg0 = (const float*)d_in[4];
    const float* W_chg1 = (const float*)d_in[5];
    const float* b_chg1 = (const float*)d_in[6];
    const float* W_chgr = (const float*)d_in[7];
    const float* b_chgr = (const float*)d_in[8];
    const float* W_dg0  = (const float*)d_in[9];
    const float* b_dg0  = (const float*)d_in[10];
    const float* W_dg1  = (const float*)d_in[11];
    const float* b_dg1  = (const float*)d_in[12];
    const float* W_dgr  = (const float*)d_in[13];
    const float* b_dgr  = (const float*)d_in[14];

    int Nch = in_sizes[0] / D_IN;
    int Ng  = in_sizes[1] / D_IN;
    int Nd  = in_sizes[2] / D_IN;

    float* out   = (float*)d_out;
    float* A_chg = out + (size_t)Nch * Nd;
    float* A_gd  = A_chg + (size_t)Nch * Ng;

    precompute_kernel<<<HB_BLOCKS + W1_BLOCKS, 256>>>(
        X_ch, X_g, X_d, W_chg0, b_chg0, W_dg0, b_dg0, W_chg1, W_dg1);

    cudaFuncSetAttribute(pair_mlp_mma,
                         cudaFuncAttributeMaxDynamicSharedMemorySize, SMEM_PAIR);
    cudaFuncSetAttribute(gemm_sigmoid_tc,
                         cudaFuncAttributeMaxDynamicSharedMemorySize, SMEM_GEMM);

    pair_mlp_mma<<<dim3(Ng / 256, Nch / 4, 2), 256, SMEM_PAIR>>>(
        b_chg1, W_chgr, b_chgr, A_chg,
        b_dg1,  W_dgr,  b_dgr,  A_gd, Ng);

    gemm_sigmoid_tc<<<dim3(Nd / 64, Nch / 64), 256, SMEM_GEMM>>>(
        out, Nch, Nd, Ng);
}

// round 17
// speedup vs baseline: 1.0358x; 1.0358x over previous
#include <cuda_runtime.h>
#include <cuda_bf16.h>
#include <math.h>
#include <stdint.h>

#define D_IN 5
#define H0 128
#define H1 64

// scratch: 4 arrays of [1024][128] fp32 (hl_chg, hr_chg, hl_dg, hr_dg)
__device__ float g_hbuf[4 * 1024 * 128];
// W1 hi/lo bf16, n-major padded: [branch][hi/lo][64 rows][136 cols]
__device__ __align__(16) __nv_bfloat16 g_w1[2][2][64 * 136];
// pre-split gemm operands: [op A/B][hi/lo][1024*1024] bf16
__device__ __align__(16) __nv_bfloat16 g_ops[2][2][1024 * 1024];

// ---------------------------------------------------------------------------
// PTX helpers (architecture-portable, sm_80-level)
// ---------------------------------------------------------------------------
__device__ __forceinline__ void mma_bf16(
    float& d0, float& d1, float& d2, float& d3,
    uint32_t a0, uint32_t a1, uint32_t a2, uint32_t a3,
    uint32_t b0, uint32_t b1)
{
    asm volatile(
        "mma.sync.aligned.m16n8k16.row.col.f32.bf16.bf16.f32 "
        "{%0,%1,%2,%3}, {%4,%5,%6,%7}, {%8,%9}, {%0,%1,%2,%3};"
        : "+f"(d0), "+f"(d1), "+f"(d2), "+f"(d3)
        : "r"(a0), "r"(a1), "r"(a2), "r"(a3), "r"(b0), "r"(b1));
}

// round-nearest split (W1 / gemm operands)
__device__ __forceinline__ void split2(float a, float b, uint32_t& hi, uint32_t& lo) {
    __nv_bfloat162 h = __float22bfloat162_rn(make_float2(a, b));
    float ra = a - __bfloat162float(h.x);
    float rb = b - __bfloat162float(h.y);
    __nv_bfloat162 l = __float22bfloat162_rn(make_float2(ra, rb));
    hi = *reinterpret_cast<uint32_t*>(&h);
    lo = *reinterpret_cast<uint32_t*>(&l);
}

// truncation split (pair act-gen hot path)
__device__ __forceinline__ void split2t(float a, float b, uint32_t& hi, uint32_t& lo) {
    uint32_t ia = __float_as_uint(a), ib = __float_as_uint(b);
    uint32_t h;
    asm("prmt.b32 %0, %1, %2, 0x7632;" : "=r"(h) : "r"(ia), "r"(ib));
    float ha = __uint_as_float(ia & 0xFFFF0000u);
    float hb = __uint_as_float(ib & 0xFFFF0000u);
    __nv_bfloat162 l = __float22bfloat162_rn(make_float2(a - ha, b - hb));
    hi = h;
    lo = *reinterpret_cast<uint32_t*>(&l);
}

__device__ __forceinline__ uint32_t smem_u32(const void* p) {
    uint32_t a;
    asm("{ .reg .u64 t; cvta.to.shared.u64 t, %1; cvt.u32.u64 %0, t; }"
        : "=r"(a) : "l"(p));
    return a;
}
__device__ __forceinline__ void cp_async16(uint32_t dst, const void* src) {
    asm volatile("cp.async.cg.shared.global [%0], [%1], 16;"
                 :: "r"(dst), "l"(src));
}
#define CP_COMMIT() asm volatile("cp.async.commit_group;" ::: "memory")
#define CP_WAIT(n)  asm volatile("cp.async.wait_group %0;" :: "n"(n) : "memory")

__device__ __forceinline__ void ldsm_x4(uint32_t& r0, uint32_t& r1,
                                        uint32_t& r2, uint32_t& r3, uint32_t a) {
    asm volatile("ldmatrix.sync.aligned.m8n8.x4.shared.b16 {%0,%1,%2,%3}, [%4];"
                 : "=r"(r0), "=r"(r1), "=r"(r2), "=r"(r3) : "r"(a));
}
__device__ __forceinline__ void ldsm_x4t(uint32_t& r0, uint32_t& r1,
                                         uint32_t& r2, uint32_t& r3, uint32_t a) {
    asm volatile("ldmatrix.sync.aligned.m8n8.x4.trans.shared.b16 {%0,%1,%2,%3}, [%4];"
                 : "=r"(r0), "=r"(r1), "=r"(r2), "=r"(r3) : "r"(a));
}
__device__ __forceinline__ uint32_t sw128(uint32_t bo) {
    return bo ^ ((bo >> 3) & 0x70);
}

// ---------------------------------------------------------------------------
// Kernel 1: flat element-parallel precompute (hbuf + W1 split)
// ---------------------------------------------------------------------------
#define HB_BLOCKS 2048
#define W1_ELEMS  (64 * 136)
#define W1_BLOCKS ((2 * W1_ELEMS + 255) / 256)

__global__ __launch_bounds__(256) void precompute_kernel(
    const float* __restrict__ X_ch, const float* __restrict__ X_g,
    const float* __restrict__ X_d,
    const float* __restrict__ W_chg0, const float* __restrict__ b_chg0,
    const float* __restrict__ W_dg0,  const float* __restrict__ b_dg0,
    const float* __restrict__ W_chg1, const float* __restrict__ W_dg1)
{
    int bid = blockIdx.x;
    if (bid < HB_BLOCKS) {
        int idx = bid * 256 + threadIdx.x;
        int a   = idx >> 17;
        int rem = idx & 131071;
        int row = rem >> 7;
        int k   = rem & 127;

        const float* X; const float* W; const float* b = nullptr;
        int woff;
        if (a == 0)      { X = X_ch; W = W_chg0; b = b_chg0; woff = 0; }
        else if (a == 1) { X = X_g;  W = W_chg0;             woff = D_IN; }
        else if (a == 2) { X = X_g;  W = W_dg0;  b = b_dg0;  woff = 0; }
        else             { X = X_d;  W = W_dg0;              woff = D_IN; }

        float v = b ? b[k] : 0.0f;
#pragma unroll
        for (int d = 0; d < D_IN; d++)
            v = fmaf(__ldg(&X[row * D_IN + d]), W[(woff + d) * H0 + k], v);
        g_hbuf[idx] = v;
    } else {
        int i = (bid - HB_BLOCKS) * 256 + threadIdx.x;
        if (i >= 2 * W1_ELEMS) return;
        int br = i / W1_ELEMS;
        int j  = i - br * W1_ELEMS;
        const float* W = br ? W_dg1 : W_chg1;
        int n = j / 136, kk = j % 136;
        float v = (kk < H0) ? W[kk * H1 + n] : 0.0f;
        __nv_bfloat16 h = __float2bfloat16(v);
        __nv_bfloat16 l = __float2bfloat16(v - __bfloat162float(h));
        g_w1[br][0][j] = h;
        g_w1[br][1][j] = l;
    }
}

// ---------------------------------------------------------------------------
// Kernel 2: pair MLP (R15 best config): bf16 3-product MMA (trunc split A),
// 256 threads (8 warps) = 4 l x 2 r-halves, 16 pairs x 64 n per warp,
// r-tile 128 (4 riters), B via ldmatrix, shr cp.async double-buffered.
// ---------------------------------------------------------------------------
#define PAIR_SHR0  34816
#define PAIR_SHRSZ 17408
#define SMEM_PAIR  74240

__global__ __launch_bounds__(256, 3) void pair_mlp_mma(
    const float* __restrict__ b1a, const float* __restrict__ Wra,
    const float* __restrict__ bra, float* __restrict__ Aa,
    const float* __restrict__ b1b, const float* __restrict__ Wrb,
    const float* __restrict__ brb, float* __restrict__ Ab,
    int R)
{
    extern __shared__ char smem[];
    __nv_bfloat16* sw1hi = (__nv_bfloat16*)smem;
    float* shl = (float*)(smem + 69632);
    float* sb1 = (float*)(smem + 73728);
    float* swr = (float*)(smem + 73984);
    const uint32_t sbase = smem_u32(smem);

    const int branch = blockIdx.z;
    const float* g_hl = g_hbuf + (branch ? 2 : 0) * 1024 * H0;
    const float* g_hr = g_hbuf + (branch ? 3 : 1) * 1024 * H0;
    const float* b1 = branch ? b1b : b1a;
    const float* Wr = branch ? Wrb : Wra;
    const float* br = branch ? brb : bra;
    float* A = branch ? Ab : Aa;
    __nv_bfloat16* opHi = g_ops[branch][0];
    __nv_bfloat16* opLo = g_ops[branch][1];

    const int t    = threadIdx.x;
    const int wid  = t >> 5;
    const int lane = t & 31;
    const int lw   = wid >> 1;
    const int rh   = wid & 1;
    const int l0   = blockIdx.y * 4;
    const int rblk = blockIdx.x * 128;

    {
        const uint4* gw = (const uint4*)g_w1[branch][0];
        uint4* sw = (uint4*)sw1hi;
        for (int i = t; i < 2176; i += 256) sw[i] = gw[i];
    }
    if (t < 128) ((float4*)shl)[t] = ((const float4*)(g_hl + (size_t)l0 * H0))[t];
    if (t >= 128 && t < 128 + H1) { sb1[t - 128] = b1[t - 128]; swr[t - 128] = Wr[t - 128]; }

    const float* shl_l = shl + lw * H0;
    const float brv = br[0];

    const int kq = (lane & 3) * 2;
    const int rq = lane >> 2;

    const int btile = lane >> 3;
    const int bnoff = (btile >> 1) * 8 + (lane & 7);
    const int bkoff = (btile & 1) * 8;

    auto stage = [&](int riter, int buf) {
        const int rb = rblk + riter * 32;
        uint32_t dst0 = sbase + PAIR_SHR0 + buf * PAIR_SHRSZ;
#pragma unroll
        for (int i = t; i < 1024; i += 256) {
            int row = i >> 5, c4 = i & 31;
            cp_async16(dst0 + (uint32_t)(row * 136 + c4 * 4) * 4u,
                       g_hr + (size_t)(rb + row) * H0 + c4 * 4);
        }
    };

    stage(0, 0);
    CP_COMMIT();

    for (int riter = 0; riter < 4; riter++) {
        __syncthreads();
        if (riter + 1 < 4) {
            stage(riter + 1, (riter + 1) & 1);
            CP_COMMIT();
            CP_WAIT(1);
        } else {
            CP_WAIT(0);
        }
        __syncthreads();

        const float* shr = (const float*)(smem + PAIR_SHR0 + (riter & 1) * PAIR_SHRSZ);
        const int rbase = rblk + riter * 32;

        float acc[8][4];
#pragma unroll
        for (int nt = 0; nt < 8; nt++)
#pragma unroll
            for (int c = 0; c < 4; c++) acc[nt][c] = 0.0f;

#pragma unroll
        for (int kt = 0; kt < 8; kt++) {
            const int kk = kt * 16 + kq;

            uint32_t ahi[4], alo[4];
            {
                float2 y0 = *(const float2*)(shl_l + kk);
                float2 y1 = *(const float2*)(shl_l + kk + 8);
                int r_lo = rh * 16 + rq;
                const float* p0 = shr + r_lo * 136 + kk;
                const float* p1 = shr + (r_lo + 8) * 136 + kk;
                float2 x00 = *(const float2*)p0;
                float2 x01 = *(const float2*)(p0 + 8);
                float2 x10 = *(const float2*)p1;
                float2 x11 = *(const float2*)(p1 + 8);
                split2t(fmaxf(x00.x + y0.x, 0.f), fmaxf(x00.y + y0.y, 0.f),
                        ahi[0], alo[0]);
                split2t(fmaxf(x10.x + y0.x, 0.f), fmaxf(x10.y + y0.y, 0.f),
                        ahi[1], alo[1]);
                split2t(fmaxf(x01.x + y1.x, 0.f), fmaxf(x01.y + y1.y, 0.f),
                        ahi[2], alo[2]);
                split2t(fmaxf(x11.x + y1.x, 0.f), fmaxf(x11.y + y1.y, 0.f),
                        ahi[3], alo[3]);
            }

#pragma unroll
            for (int g = 0; g < 4; g++) {
                uint32_t boff = (uint32_t)((g * 16 + bnoff) * 136
                                           + kt * 16 + bkoff) * 2u;
                uint32_t bh0, bh1, bh2, bh3, bl0, bl1, bl2, bl3;
                ldsm_x4(bh0, bh1, bh2, bh3, sbase + boff);
                ldsm_x4(bl0, bl1, bl2, bl3, sbase + 17408u + boff);

                int nt0 = 2 * g, nt1 = 2 * g + 1;
                mma_bf16(acc[nt0][0], acc[nt0][1], acc[nt0][2], acc[nt0][3],
                         ahi[0], ahi[1], ahi[2], ahi[3], bh0, bh1);
                mma_bf16(acc[nt0][0], acc[nt0][1], acc[nt0][2], acc[nt0][3],
                         ahi[0], ahi[1], ahi[2], ahi[3], bl0, bl1);
                mma_bf16(acc[nt0][0], acc[nt0][1], acc[nt0][2], acc[nt0][3],
                         alo[0], alo[1], alo[2], alo[3], bh0, bh1);
                mma_bf16(acc[nt1][0], acc[nt1][1], acc[nt1][2], acc[nt1][3],
                         ahi[0], ahi[1], ahi[2], ahi[3], bh2, bh3);
                mma_bf16(acc[nt1][0], acc[nt1][1], acc[nt1][2], acc[nt1][3],
                         ahi[0], ahi[1], ahi[2], ahi[3], bl2, bl3);
                mma_bf16(acc[nt1][0], acc[nt1][1], acc[nt1][2], acc[nt1][3],
                         alo[0], alo[1], alo[2], alo[3], bh2, bh3);
            }
        }

        // epilogue
        {
            float s0 = 0.0f, s1 = 0.0f;
#pragma unroll
            for (int nt = 0; nt < 8; nt++) {
                int j0 = nt * 8 + kq;
                float bb0 = sb1[j0], bb1 = sb1[j0 + 1];
                float ww0 = swr[j0], ww1 = swr[j0 + 1];
                s0 = fmaf(fmaxf(acc[nt][0] + bb0, 0.f), ww0, s0);
                s0 = fmaf(fmaxf(acc[nt][1] + bb1, 0.f), ww1, s0);
                s1 = fmaf(fmaxf(acc[nt][2] + bb0, 0.f), ww0, s1);
                s1 = fmaf(fmaxf(acc[nt][3] + bb1, 0.f), ww1, s1);
            }
            s0 += __shfl_xor_sync(0xffffffffu, s0, 1);
            s0 += __shfl_xor_sync(0xffffffffu, s0, 2);
            s1 += __shfl_xor_sync(0xffffffffu, s1, 1);
            s1 += __shfl_xor_sync(0xffffffffu, s1, 2);
            if ((lane & 3) == 0) {
                int r_lo = rbase + rh * 16 + rq;
                float x0 = s0 + brv;
                float x1 = s1 + brv;
                float e0 = (x0 > 0.0f) ? x0 : expm1f(x0);
                float e1 = (x1 > 0.0f) ? x1 : expm1f(x1);
                size_t rowoff = (size_t)(l0 + lw) * R;
                float* arow = A + rowoff;
                arow[r_lo]     = e0;
                arow[r_lo + 8] = e1;
                __nv_bfloat16 h0 = __float2bfloat16(e0);
                __nv_bfloat16 h1 = __float2bfloat16(e1);
                opHi[rowoff + r_lo]     = h0;
                opHi[rowoff + r_lo + 8] = h1;
                opLo[rowoff + r_lo]     = __float2bfloat16(e0 - __bfloat162float(h0));
                opLo[rowoff + r_lo + 8] = __float2bfloat16(e1 - __bfloat162float(h1));
            }
        }
    }
}

// ---------------------------------------------------------------------------
// Kernel 3: C = sigmoid(A @ B), bf16 3-product MMA, operands pre-split.
// 64m x 64n CTA tiles (256 CTAs), 32KB/stage double-buffered.
// occupancy cap 3 (register cap 85) for better stage/compute overlap.
// ---------------------------------------------------------------------------
#define GS_STAGE 32768
#define GS_ALO   8192
#define GS_BHI   16384
#define GS_BLO   24576
#define SMEM_GEMM (2 * GS_STAGE)

__global__ __launch_bounds__(256, 3) void gemm_sigmoid_tc(
    float* __restrict__ C, int M, int N, int K)
{
    extern __shared__ char smem[];
    const uint32_t sb = smem_u32(smem);

    const __nv_bfloat16* gAhi = g_ops[0][0];
    const __nv_bfloat16* gAlo = g_ops[0][1];
    const __nv_bfloat16* gBhi = g_ops[1][0];
    const __nv_bfloat16* gBlo = g_ops[1][1];

    const int t    = threadIdx.x;
    const int wid  = t >> 5;
    const int lane = t & 31;
    const int m0 = blockIdx.y * 64, n0 = blockIdx.x * 64;
    const int wm = (wid >> 2) * 32;
    const int wn = (wid & 3) * 16;
    const int kq = (lane & 3) * 2;
    const int rq = lane >> 2;

    float acc[2][2][4];
#pragma unroll
    for (int mh = 0; mh < 2; mh++)
#pragma unroll
        for (int nt = 0; nt < 2; nt++)
#pragma unroll
            for (int c = 0; c < 4; c++) acc[mh][nt][c] = 0.0f;

    const int K64 = K >> 6;

    auto stage = [&](int kb, int buf) {
        uint32_t base = sb + buf * GS_STAGE;
#pragma unroll
        for (int i = t; i < 512; i += 256) {
            int m = i >> 3, c = i & 7;
            uint32_t sw = sw128((uint32_t)(m * 128 + c * 16));
            size_t off = (size_t)(m0 + m) * K + kb * 64 + c * 8;
            cp_async16(base + sw, gAhi + off);
            cp_async16(base + GS_ALO + sw, gAlo + off);
        }
#pragma unroll
        for (int i = t; i < 512; i += 256) {
            int k = i >> 3, c = i & 7;
            uint32_t sw = sw128((uint32_t)(k * 128 + c * 16));
            size_t off = (size_t)(kb * 64 + k) * N + n0 + c * 8;
            cp_async16(base + GS_BHI + sw, gBhi + off);
            cp_async16(base + GS_BLO + sw, gBlo + off);
        }
    };

    stage(0, 0);
    CP_COMMIT();

    for (int kb = 0; kb < K64; kb++) {
        if (kb + 1 < K64) {
            stage(kb + 1, (kb + 1) & 1);
            CP_COMMIT();
            CP_WAIT(1);
        } else {
            CP_WAIT(0);
        }
        __syncthreads();

        uint32_t base = sb + (kb & 1) * GS_STAGE;
#pragma unroll
        for (int kt = 0; kt < 4; kt++) {
            uint32_t ahi[2][4], alo[2][4];
#pragma unroll
            for (int mh = 0; mh < 2; mh++) {
                int row = wm + mh * 16 + (lane & 15);
                uint32_t sw = sw128((uint32_t)(row * 128 + kt * 32 + (lane >> 4) * 16));
                ldsm_x4(ahi[mh][0], ahi[mh][1], ahi[mh][2], ahi[mh][3], base + sw);
                ldsm_x4(alo[mh][0], alo[mh][1], alo[mh][2], alo[mh][3],
                        base + GS_ALO + sw);
            }
            uint32_t bh[2][2], bl[2][2];
            {
                int krow = kt * 16 + (lane & 15);
                uint32_t sw = sw128((uint32_t)(krow * 128 + wn * 2
                                               + (lane >> 4) * 16));
                uint32_t r0, r1, r2, r3;
                ldsm_x4t(r0, r1, r2, r3, base + GS_BHI + sw);
                bh[0][0] = r0; bh[0][1] = r1; bh[1][0] = r2; bh[1][1] = r3;
                ldsm_x4t(r0, r1, r2, r3, base + GS_BLO + sw);
                bl[0][0] = r0; bl[0][1] = r1; bl[1][0] = r2; bl[1][1] = r3;
            }
#pragma unroll
            for (int nt = 0; nt < 2; nt++)
#pragma unroll
                for (int mh = 0; mh < 2; mh++) {
                    mma_bf16(acc[mh][nt][0], acc[mh][nt][1],
                             acc[mh][nt][2], acc[mh][nt][3],
                             ahi[mh][0], ahi[mh][1], ahi[mh][2], ahi[mh][3],
                             bh[nt][0], bh[nt][1]);
                    mma_bf16(acc[mh][nt][0], acc[mh][nt][1],
                             acc[mh][nt][2], acc[mh][nt][3],
                             ahi[mh][0], ahi[mh][1], ahi[mh][2], ahi[mh][3],
                             bl[nt][0], bl[nt][1]);
                    mma_bf16(acc[mh][nt][0], acc[mh][nt][1],
                             acc[mh][nt][2], acc[mh][nt][3],
                             alo[mh][0], alo[mh][1], alo[mh][2], alo[mh][3],
                             bh[nt][0], bh[nt][1]);
                }
        }
        __syncthreads();
    }

#pragma unroll
    for (int mh = 0; mh < 2; mh++)
#pragma unroll
        for (int nt = 0; nt < 2; nt++) {
            int row = m0 + wm + mh * 16 + rq;
            int col = n0 + wn + nt * 8 + kq;
            float* r0p = &C[(size_t)row * N + col];
            float* r1p = &C[(size_t)(row + 8) * N + col];
            r0p[0] = 1.0f / (1.0f + __expf(-acc[mh][nt][0]));
            r0p[1] = 1.0f / (1.0f + __expf(-acc[mh][nt][1]));
            r1p[0] = 1.0f / (1.0f + __expf(-acc[mh][nt][2]));
            r1p[1] = 1.0f / (1.0f + __expf(-acc[mh][nt][3]));
        }
}

// ---------------------------------------------------------------------------
// Launch
// ---------------------------------------------------------------------------
extern "C" void kernel_launch(void* const* d_in, const int* in_sizes, int n_in,
                              void* d_out, int out_size)
{
    const float* X_ch   = (const float*)d_in[0];
    const float* X_g    = (const float*)d_in[1];
    const float* X_d    = (const float*)d_in[2];
    const float* W_chg0 = (const float*)d_in[3];
    const float* b_chg0 = (const float*)d_in[4];
    const float* W_chg1 = (const float*)d_in[5];
    const float* b_chg1 = (const float*)d_in[6];
    const float* W_chgr = (const float*)d_in[7];
    const float* b_chgr = (const float*)d_in[8];
    const float* W_dg0  = (const float*)d_in[9];
    const float* b_dg0  = (const float*)d_in[10];
    const float* W_dg1  = (const float*)d_in[11];
    const float* b_dg1  = (const float*)d_in[12];
    const float* W_dgr  = (const float*)d_in[13];
    const float* b_dgr  = (const float*)d_in[14];

    int Nch = in_sizes[0] / D_IN;
    int Ng  = in_sizes[1] / D_IN;
    int Nd  = in_sizes[2] / D_IN;

    float* out   = (float*)d_out;
    float* A_chg = out + (size_t)Nch * Nd;
    float* A_gd  = A_chg + (size_t)Nch * Ng;

    precompute_kernel<<<HB_BLOCKS + W1_BLOCKS, 256>>>(
        X_ch, X_g, X_d, W_chg0, b_chg0, W_dg0, b_dg0, W_chg1, W_dg1);

    cudaFuncSetAttribute(pair_mlp_mma,
                         cudaFuncAttributeMaxDynamicSharedMemorySize, SMEM_PAIR);
    cudaFuncSetAttribute(gemm_sigmoid_tc,
                         cudaFuncAttributeMaxDynamicSharedMemorySize, SMEM_GEMM);

    pair_mlp_mma<<<dim3(Ng / 128, Nch / 4, 2), 256, SMEM_PAIR>>>(
        b_chg1, W_chgr, b_chgr, A_chg,
        b_dg1,  W_dgr,  b_dgr,  A_gd, Ng);

    gemm_sigmoid_tc<<<dim3(Nd / 64, Nch / 64), 256, SMEM_GEMM>>>(
        out, Nch, Nd, Ng);
}